// round 17
// baseline (speedup 1.0000x reference)
#include <cuda_runtime.h>
#include <cstdint>

#define BS    8
#define CDIM  256
#define SP    16384            // 16*32*32 spatial per batch
#define NTOK  (BS * SP)        // 131072
#define NCODE 1024
#define NQ    (BS * CDIM * SP) // 33554432

#define MT     128             // tokens per screen block
#define ZPB    264             // smem row stride bytes (66 words -> bank stride 2)
#define SCODES 128             // codes per stage
#define NSTAGE (NCODE / SCODES) // 8
#define MAXCAND 48             // R16 failed with 16: shallow-min tokens have ~17-25 in-margin codes
#define KEEP   6               // per-owner top-k
#define ECQ    3.8447e-6f      // 0.5/(127*1024)
#define CSCALE 130048.0f       // 127*1024
#define EPS_REF 2.0e-4f        // reference-epilogue rounding + fp slop cushion

__device__ float g_cnorm[NCODE];
__device__ float g_cl1[NCODE];
__device__ unsigned int g_cl1max;
__device__ int   g_idx[NTOK];
__device__ __align__(16) char g_cbi[NCODE * CDIM];  // int8 codebook [code][k]

// ---------------- helpers (sm_103-safe) ------------------------------------
#define CP_ASYNC8(dst, src) asm volatile("cp.async.ca.shared.global [%0], [%1], 8;" :: "r"(dst), "l"(src) : "memory")
#define CP_COMMIT()         asm volatile("cp.async.commit_group;" ::: "memory")
#define CP_WAIT0()          asm volatile("cp.async.wait_group 0;" ::: "memory")

__device__ __forceinline__ uint32_t smem_u32(const void* p) {
    uint32_t a;
    asm("{ .reg .u64 t; cvta.to.shared.u64 t, %1; cvt.u32.u64 %0, t; }" : "=r"(a) : "l"(p));
    return a;
}
__device__ __forceinline__ uint32_t fenc(float f) {
    uint32_t u = __float_as_uint(f);
    return (u >> 31) ? ~u : (u | 0x80000000u);
}
__device__ __forceinline__ float fdec(uint32_t k) {
    uint32_t u = (k >> 31) ? (k & 0x7fffffffu) : ~k;
    return __uint_as_float(u);
}
__device__ __forceinline__ void ins6(float v, int j, float* bv, int* bi) {
    if (v < bv[KEEP - 1]) {
        bv[KEEP - 1] = v; bi[KEEP - 1] = j;
#pragma unroll
        for (int q = KEEP - 2; q >= 0; --q) {
            if (bv[q + 1] < bv[q]) {
                float tv = bv[q]; bv[q] = bv[q + 1]; bv[q + 1] = tv;
                int   ti = bi[q]; bi[q] = bi[q + 1]; bi[q + 1] = ti;
            }
        }
    }
}

// ---------------------------------------------------------------------------
// per-code: exact ||c||^2 (bit-exact recipe), L1(c), global max L1  [R9-pass]
// ---------------------------------------------------------------------------
__global__ void cnorm_kernel(const float* __restrict__ cb) {
    int r = blockIdx.x * 256 + threadIdx.x;
    const float* row = cb + (size_t)r * CDIM;
    float s = 0.f, l1 = 0.f;
#pragma unroll 8
    for (int k = 0; k < CDIM; ++k) {
        float v = row[k];
        s = __fadd_rn(s, __fmul_rn(v, v));
        l1 += fabsf(v);
    }
    g_cnorm[r] = s; g_cl1[r] = l1;
    atomicMax(&g_cl1max, fenc(l1));
}

// int8 codebook quantization  [R9-pass]
__global__ void cbi_kernel(const float* __restrict__ cb) {
    int i = blockIdx.x * 256 + threadIdx.x;
    int q = __float2int_rn(cb[i] * CSCALE);
    g_cbi[i] = (char)max(-127, min(127, q));
}

// ---------------------------------------------------------------------------
// dp4a screen: 512 thr uniform. thread (tg,cg): tokens tg*4..+3, codes cg+16m.
// 8 stages x 128 codes, double-buffered 8B cp.async. Inline margin+rescore.
// ---------------------------------------------------------------------------
#define CBST_B   (SCODES * ZPB)                    // 33792
#define SM_Z8    0                                 // [128][264] int8
#define SM_CB    (MT * ZPB)                        // 33792
#define SM_CNS   (SM_CB + 2 * CBST_B)              // 101376
#define SM_CL1   (SM_CNS + NCODE * 4)              // 105472
#define SM_MAXP  (SM_CL1 + NCODE * 4)              // 109568
#define SM_L1P   (SM_MAXP + 4 * MT * 4)            // 111616
#define SM_FCT   (SM_L1P + 4 * MT * 4)             // 113664
#define SM_EZN   (SM_FCT + MT * 4)                 // 114176
#define SM_L1Z   (SM_EZN + MT * 4)                 // 114688
#define SM_RCP   (SM_L1Z + MT * 4)                 // 115200
#define SM_MINK  (SM_RCP + MT * 4)                 // 115712
#define SM_CCNT  (SM_MINK + MT * 4)                // 116224
#define SM_CAND  (SM_CCNT + MT * 4)                // 116736
#define SM_TOTAL (SM_CAND + MT * MAXCAND * 4)      // 141312

__global__ __launch_bounds__(512, 1)
void screen_kernel(const float* __restrict__ z, const float* __restrict__ cb,
                   float* __restrict__ oidx)
{
    extern __shared__ char smem[];
    char*  z8  = smem + SM_Z8;
    float* cns = (float*)(smem + SM_CNS);
    float* cl1 = (float*)(smem + SM_CL1);
    float* maxp = (float*)(smem + SM_MAXP);
    float* l1p  = (float*)(smem + SM_L1P);
    float* fct  = (float*)(smem + SM_FCT);
    float* ezn  = (float*)(smem + SM_EZN);
    float* l1z  = (float*)(smem + SM_L1Z);
    float* rcp  = (float*)(smem + SM_RCP);
    uint32_t* minkey = (uint32_t*)(smem + SM_MINK);
    int* candcnt = (int*)(smem + SM_CCNT);
    int* cand    = (int*)(smem + SM_CAND);

    const int tid = threadIdx.x;
    const int tg = tid >> 4, cg = tid & 15;       // 32 tokgroups x 16 codegroups
    const int t0 = tg * 4;
    const int n0 = blockIdx.x * MT;
    const int b  = n0 / SP, s0 = n0 % SP;
    const float* zbase = z + (size_t)b * CDIM * SP + s0;
    const float cl1maxv = fdec(g_cl1max);
    const uint32_t cbu = smem_u32(smem + SM_CB);

    // ---- prologue pass 1: per-token maxabs + L1 partials ----
    {
        const int tok = tid & 127, grp = tid >> 7;   // 4 threads per token
        float mx = 0.f, l1 = 0.f;
        for (int k = grp; k < CDIM; k += 4) {
            float v = fabsf(zbase[(size_t)k * SP + tok]);
            mx = fmaxf(mx, v); l1 += v;
        }
        maxp[grp * MT + tok] = mx;
        l1p[grp * MT + tok] = l1;
    }
    for (int i = tid; i < NCODE; i += 512) { cns[i] = g_cnorm[i]; cl1[i] = g_cl1[i]; }
    if (tid < MT) { minkey[tid] = 0xFFFFFFFFu; candcnt[tid] = 0; }
    // stage-0 cp.async: 128 codes x 256B in 8B chunks
    {
        const char* src = g_cbi;
#pragma unroll
        for (int it = 0; it < 8; ++it) {
            int id = tid + it * 512;                 // 0..4095
            int cc = id >> 5, ch = id & 31;
            CP_ASYNC8(cbu + (uint32_t)(cc * ZPB + ch * 8), src + cc * CDIM + ch * 8);
        }
        CP_COMMIT();
    }
    __syncthreads();

    // ---- per-token scale ----
    if (tid < MT) {
        float mx = fmaxf(fmaxf(maxp[tid], maxp[MT + tid]),
                         fmaxf(maxp[2 * MT + tid], maxp[3 * MT + tid]));
        float l1 = l1p[tid] + l1p[MT + tid] + l1p[2 * MT + tid] + l1p[3 * MT + tid];
        float step = fmaxf(mx, 1e-30f) * (1.0f / 127.0f);
        rcp[tid] = 1.0f / step;
        fct[tid] = step * (2.0f / CSCALE);
        ezn[tid] = step * 0.5f;
        l1z[tid] = l1;
    }
    __syncthreads();

    // ---- prologue pass 2: quantize z tile ----
    {
        const int tok = tid & 127, grp = tid >> 7;
        float rc = rcp[tok];
        for (int kc = grp; kc < 64; kc += 4) {
            uint32_t w = 0;
#pragma unroll
            for (int kk = 0; kk < 4; ++kk) {
                int k = kc * 4 + kk;
                int q = __float2int_rn(zbase[(size_t)k * SP + tok] * rc);
                q = max(-127, min(127, q));
                w |= (uint32_t)(q & 0xFF) << (kk * 8);
            }
            *(uint32_t*)(z8 + tok * ZPB + kc * 4) = w;
        }
    }
    CP_WAIT0();
    __syncthreads();

    float f4[4];
#pragma unroll
    for (int i = 0; i < 4; ++i) f4[i] = fct[t0 + i];

    float bv[4][KEEP]; int bi4[4][KEEP];
#pragma unroll
    for (int s = 0; s < 4; ++s)
#pragma unroll
        for (int q = 0; q < KEEP; ++q) { bv[s][q] = 3.4e38f; bi4[s][q] = 0; }

    for (int st = 0; st < NSTAGE; ++st) {
        if (st + 1 < NSTAGE) {
            const char* src = g_cbi + (size_t)(st + 1) * SCODES * CDIM;
            uint32_t dstb = cbu + ((st + 1) & 1) * CBST_B;
#pragma unroll
            for (int it = 0; it < 8; ++it) {
                int id = tid + it * 512;
                int cc = id >> 5, ch = id & 31;
                CP_ASYNC8(dstb + (uint32_t)(cc * ZPB + ch * 8), src + cc * CDIM + ch * 8);
            }
        }
        CP_COMMIT();

        // ---- compute: 4 tok x 8 codes per thread, uint2 (8B) loads ----
        const char* cbuf = smem + SM_CB + (st & 1) * CBST_B;
        int acc[4][8];
#pragma unroll
        for (int i = 0; i < 4; ++i)
#pragma unroll
            for (int m = 0; m < 8; ++m) acc[i][m] = 0;

#pragma unroll 2
        for (int kc = 0; kc < 16; ++kc) {
            uint2 za[4], zb[4];
#pragma unroll
            for (int i = 0; i < 4; ++i) {
                const char* zr = z8 + (t0 + i) * ZPB + kc * 16;
                za[i] = *(const uint2*)(zr);
                zb[i] = *(const uint2*)(zr + 8);
            }
#pragma unroll
            for (int m = 0; m < 8; ++m) {
                const char* crp = cbuf + (cg + 16 * m) * ZPB + kc * 16;
                uint2 ca = *(const uint2*)(crp);
                uint2 cb2 = *(const uint2*)(crp + 8);
#pragma unroll
                for (int i = 0; i < 4; ++i) {
                    acc[i][m] = __dp4a((int)za[i].x, (int)ca.x,  acc[i][m]);
                    acc[i][m] = __dp4a((int)za[i].y, (int)ca.y,  acc[i][m]);
                    acc[i][m] = __dp4a((int)zb[i].x, (int)cb2.x, acc[i][m]);
                    acc[i][m] = __dp4a((int)zb[i].y, (int)cb2.y, acc[i][m]);
                }
            }
        }

        // ---- epilogue: 32 scores/thread, per-token-slot top-6 ----
        int jb = st * SCODES + cg;
#pragma unroll
        for (int m = 0; m < 8; ++m) {
            int j = jb + 16 * m;
            float cn = cns[j];
#pragma unroll
            for (int i = 0; i < 4; ++i)
                ins6(cn - f4[i] * (float)acc[i][m], j, bv[i], bi4[i]);
        }

        CP_WAIT0();
        __syncthreads();
    }

    // ---- per-token screened min (16 owners per token) ----
#pragma unroll
    for (int i = 0; i < 4; ++i) atomicMin(&minkey[t0 + i], fenc(bv[i][0]));
    __syncthreads();

    // ---- append candidates within deterministic margin (R9 formula) ----
#pragma unroll
    for (int i = 0; i < 4; ++i) {
        int tokl = t0 + i;
        float ez = ezn[tokl];
        float thrbase = fdec(minkey[tokl]) + 4.0f * ECQ * l1z[tokl]
                      + 4.0f * 256.0f * ez * ECQ + EPS_REF;
#pragma unroll
        for (int q = 0; q < KEEP; ++q) {
            float thr = thrbase + 2.0f * ez * (cl1[bi4[i][q]] + cl1maxv);
            if (bv[i][q] <= thr) {
                int pos = atomicAdd(&candcnt[tokl], 1);
                if (pos < MAXCAND) cand[tokl * MAXCAND + pos] = bi4[i][q];
            }
        }
    }
    __syncthreads();

    // ---- resolve: bit-exact XLA:CPU rescore when ambiguous ----
    if (tid < MT) {
        int tok = tid;
        int cnt = candcnt[tok]; if (cnt > MAXCAND) cnt = MAXCAND;
        int best = cand[tok * MAXCAND];
        if (cnt > 1) {
            const float* zp = zbase + tok;
            float zn = 0.f;
#pragma unroll 8
            for (int k = 0; k < CDIM; ++k) {
                float v = zp[(size_t)k * SP];
                zn = __fadd_rn(zn, __fmul_rn(v, v));
            }
            float bsc = 3.4e38f; best = 0x7fffffff;
            for (int q = 0; q < cnt; ++q) {
                int j = cand[tok * MAXCAND + q];
                const float* cr = cb + (size_t)j * CDIM;
                float acc = 0.f;
#pragma unroll 8
                for (int k = 0; k < CDIM; ++k)
                    acc = __fmaf_rn(zp[(size_t)k * SP], cr[k], acc);
                float sc = __fadd_rn(__fadd_rn(zn, __fmul_rn(acc, -2.f)), cns[j]);
                if (sc < bsc || (sc == bsc && j < best)) { bsc = sc; best = j; }
            }
        }
        int n = n0 + tok;
        g_idx[n] = best;
        if (oidx) oidx[n] = (float)best;
    }
}

// ---------------------------------------------------------------------------
// gather + transpose writer (validated, 89us)
// ---------------------------------------------------------------------------
#define WT 32
#define WP 33
__global__ __launch_bounds__(256) void write_kernel(
    const float* __restrict__ cb, const float* __restrict__ z,
    float* __restrict__ outq, float* __restrict__ outst)
{
    __shared__ float tile[CDIM * WP];
    __shared__ int   sidx[WT];

    const int tid = threadIdx.x;
    const int n0  = blockIdx.x * WT;
    const int b   = n0 / SP, s0 = n0 % SP;

    if (tid < WT) sidx[tid] = g_idx[n0 + tid];
    __syncthreads();

    const int c = tid;
#pragma unroll 8
    for (int tok = 0; tok < WT; ++tok)
        tile[c * WP + tok] = cb[(size_t)sidx[tok] * CDIM + c];
    __syncthreads();

    const size_t base = (size_t)b * CDIM * SP + s0;
    const int tok4 = (tid & 7) * 4;
    int cc = tid >> 3;
#pragma unroll 8
    for (int it = 0; it < 8; ++it, cc += 32) {
        size_t addr = base + (size_t)cc * SP + tok4;
        const float* tp = &tile[cc * WP + tok4];
        float4 q = make_float4(tp[0], tp[1], tp[2], tp[3]);
        *(float4*)(outq + addr) = q;
        if (outst) {
            float4 zv = *(const float4*)(z + addr);
            float4 st;
            st.x = __fadd_rn(zv.x, __fadd_rn(q.x, -zv.x));
            st.y = __fadd_rn(zv.y, __fadd_rn(q.y, -zv.y));
            st.z = __fadd_rn(zv.z, __fadd_rn(q.z, -zv.z));
            st.w = __fadd_rn(zv.w, __fadd_rn(q.w, -zv.w));
            *(float4*)(outst + addr) = st;
        }
    }
}

// ---------------------------------------------------------------------------
extern "C" void kernel_launch(void* const* d_in, const int* in_sizes, int n_in,
                              void* d_out, int out_size) {
    const float* z  = (const float*)d_in[0];
    const float* cb = (const float*)d_in[1];
    float* out = (float*)d_out;

    float* outq   = out;
    float* outst  = nullptr;
    float* outidx = nullptr;
    if (out_size >= 2 * NQ + NTOK)      { outst = out + NQ; outidx = out + 2 * (size_t)NQ; }
    else if (out_size >= 2 * NQ)        { outst = out + NQ; }
    else if (out_size >= NQ + NTOK)     { outidx = out + NQ; }

    cudaFuncSetAttribute(screen_kernel, cudaFuncAttributeMaxDynamicSharedMemorySize, SM_TOTAL);

    cnorm_kernel<<<NCODE / 256, 256>>>(cb);
    cbi_kernel<<<NCODE * CDIM / 256, 256>>>(cb);
    screen_kernel<<<NTOK / MT, 512, SM_TOTAL>>>(z, cb, outidx);
    write_kernel<<<NTOK / WT, 256>>>(cb, z, outq, outst);
}